// round 11
// baseline (speedup 1.0000x reference)
#include <cuda_runtime.h>
#include <math.h>

// ---------------------------------------------------------------------------
// MomentPredictor: 16-step autoregressive rollout of a 2-layer causal
// transformer (B=512, D=512, H=8, FF=2048). Implemented as exact incremental
// decoding with a KV cache (causal mask + per-token LN make prefix states
// step-invariant). fp32 throughout for the 1e-3 tolerance.
// ---------------------------------------------------------------------------

#define NB   512   // batch
#define NT   16    // time steps
#define NDIN 7
#define ND   512   // model dim
#define NL   2     // layers
#define NH   8     // heads
#define NHD  64    // head dim
#define NFF  2048

// ---- scratch (device globals: no runtime allocation allowed) ----
__device__ float g_h  [NB * ND];    // current hidden
__device__ float g_h1 [NB * ND];    // post-LN1 hidden
__device__ float g_tmp[NB * ND];    // pre-LN accumulator
__device__ float g_q  [NB * ND];    // Q for current token
__device__ float g_att[NB * ND];    // attention output
__device__ float g_ff [NB * NFF];   // FF1 activations
__device__ float g_kc [NL * NB * NH * NT * NHD];  // K cache
__device__ float g_vc [NL * NB * NH * NT * NHD];  // V cache
__device__ float g_y  [NB * 3];     // feedback prediction

// ---------------------------------------------------------------------------
// embed: h[b,d] = x_t[b,:] @ ip_w + ip_b + PE(t, d)
// channels 4..6 of x_t come from g_y for t>0 (autoregressive feedback)
// ---------------------------------------------------------------------------
__global__ void embed_k(const float* __restrict__ x,
                        const float* __restrict__ ipw,
                        const float* __restrict__ ipb, int t) {
    int b = blockIdx.x;
    int d = threadIdx.x;            // 512 threads
    float xin[NDIN];
    const float* xr = x + (b * NT + t) * NDIN;
#pragma unroll
    for (int k = 0; k < NDIN; k++) xin[k] = xr[k];
    if (t > 0) {
        xin[4] = g_y[b * 3 + 0];
        xin[5] = g_y[b * 3 + 1];
        xin[6] = g_y[b * 3 + 2];
    }
    float acc = ipb[d];
#pragma unroll
    for (int k = 0; k < NDIN; k++) acc = fmaf(xin[k], ipw[k * ND + d], acc);
    // positional encoding: pe[t, 2i] = sin(t*div_i), pe[t, 2i+1] = cos(t*div_i)
    int   i2  = (d >> 1) << 1;
    float div = expf(-(float)i2 * (9.210340371976184f / 512.0f)); // ln(1e4)/D
    float ang = (float)t * div;
    acc += (d & 1) ? cosf(ang) : sinf(ang);
    g_h[b * ND + d] = acc;
}

// ---------------------------------------------------------------------------
// sgemm64: 64x64 tile, BK=16, 256 threads, 4x4 per thread (float4 smem reads)
// MODE 0: QKV — A=g_h, N=1536; epilogue scatters Q / K-cache / V-cache
// MODE 1: FF1 — A=g_h1, N=2048; epilogue bias + relu -> g_ff
// ---------------------------------------------------------------------------
template <int MODE>
__global__ void sgemm64_k(const float* __restrict__ W,
                          const float* __restrict__ bias,
                          int N, int K, int l, int t) {
    __shared__ __align__(16) float As[16][64];
    __shared__ __align__(16) float Bs[16][64];

    const float* A = (MODE == 0) ? g_h : g_h1;
    int tid = threadIdx.x;
    int tx = tid & 15, ty = tid >> 4;
    int bm = blockIdx.y << 6, bn = blockIdx.x << 6;

    int arow = tid >> 2,  ac4 = (tid & 3) << 2;   // A tile: 64 rows x 16 k
    int brow = tid >> 4,  bc4 = (tid & 15) << 2;  // B tile: 16 k x 64 cols

    const float* Aptr = A + (bm + arow) * K + ac4;
    const float* Wptr = W + brow * N + bn + bc4;

    float acc[4][4];
#pragma unroll
    for (int i = 0; i < 4; i++)
#pragma unroll
        for (int j = 0; j < 4; j++) acc[i][j] = 0.f;

    for (int k0 = 0; k0 < K; k0 += 16) {
        float4 av = *(const float4*)(Aptr + k0);
        As[ac4 + 0][arow] = av.x;
        As[ac4 + 1][arow] = av.y;
        As[ac4 + 2][arow] = av.z;
        As[ac4 + 3][arow] = av.w;
        float4 bv = *(const float4*)(Wptr + (size_t)k0 * N);
        *(float4*)&Bs[brow][bc4] = bv;
        __syncthreads();
#pragma unroll
        for (int k = 0; k < 16; k++) {
            float4 a = *(const float4*)&As[k][ty << 2];
            float4 b = *(const float4*)&Bs[k][tx << 2];
            float ar[4] = {a.x, a.y, a.z, a.w};
            float br[4] = {b.x, b.y, b.z, b.w};
#pragma unroll
            for (int i = 0; i < 4; i++)
#pragma unroll
                for (int j = 0; j < 4; j++)
                    acc[i][j] = fmaf(ar[i], br[j], acc[i][j]);
        }
        __syncthreads();
    }

#pragma unroll
    for (int i = 0; i < 4; i++) {
        int m = bm + (ty << 2) + i;
#pragma unroll
        for (int j = 0; j < 4; j++) {
            int col = bn + (tx << 2) + j;
            float v = acc[i][j] + bias[col];
            if (MODE == 1) {
                g_ff[m * NFF + col] = fmaxf(v, 0.f);
            } else {
                if (col < ND) {
                    g_q[m * ND + col] = v;
                } else if (col < 2 * ND) {
                    int c = col - ND;
                    g_kc[(size_t)l * (NB * NH * NT * NHD) +
                         (size_t)((m * NH + (c >> 6)) * NT + t) * NHD + (c & 63)] = v;
                } else {
                    int c = col - 2 * ND;
                    g_vc[(size_t)l * (NB * NH * NT * NHD) +
                         (size_t)((m * NH + (c >> 6)) * NT + t) * NHD + (c & 63)] = v;
                }
            }
        }
    }
}

// ---------------------------------------------------------------------------
// sgemm32: 32x32 tile, BK=16, 64 threads, 4x4 per thread. N=512 output so
// grid = 256 blocks (covers all 148 SMs, unlike a 64-block 64x64 grid).
// mode 0: out-proj  (A=g_att, resid=g_h)   -> g_tmp
// mode 1: FF2       (A=g_ff,  resid=g_h1)  -> g_tmp
// ---------------------------------------------------------------------------
__global__ void sgemm32_k(const float* __restrict__ W,
                          const float* __restrict__ bias,
                          int K, int mode) {
    __shared__ __align__(16) float As[16][32];
    __shared__ __align__(16) float Bs[16][32];

    const float* A = mode ? g_ff : g_att;
    const float* R = mode ? g_h1 : g_h;
    const int N = ND;
    int tid = threadIdx.x;                 // 64 threads
    int tx = tid & 7, ty = tid >> 3;
    int bm = blockIdx.y << 5, bn = blockIdx.x << 5;

    float acc[4][4];
#pragma unroll
    for (int i = 0; i < 4; i++)
#pragma unroll
        for (int j = 0; j < 4; j++) acc[i][j] = 0.f;

    for (int k0 = 0; k0 < K; k0 += 16) {
#pragma unroll
        for (int r = 0; r < 2; r++) {
            int idx = tid + (r << 6);
            int row = idx >> 2, c4 = (idx & 3) << 2;           // A: 32x16
            float4 av = *(const float4*)&A[(size_t)(bm + row) * K + k0 + c4];
            As[c4 + 0][row] = av.x;
            As[c4 + 1][row] = av.y;
            As[c4 + 2][row] = av.z;
            As[c4 + 3][row] = av.w;
            int br = idx >> 3, bc = (idx & 7) << 2;            // B: 16x32
            float4 bv = *(const float4*)&W[(size_t)(k0 + br) * N + bn + bc];
            *(float4*)&Bs[br][bc] = bv;
        }
        __syncthreads();
#pragma unroll
        for (int k = 0; k < 16; k++) {
            float4 a = *(const float4*)&As[k][ty << 2];
            float4 b = *(const float4*)&Bs[k][tx << 2];
            float ar[4] = {a.x, a.y, a.z, a.w};
            float br[4] = {b.x, b.y, b.z, b.w};
#pragma unroll
            for (int i = 0; i < 4; i++)
#pragma unroll
                for (int j = 0; j < 4; j++)
                    acc[i][j] = fmaf(ar[i], br[j], acc[i][j]);
        }
        __syncthreads();
    }

#pragma unroll
    for (int i = 0; i < 4; i++) {
        int m = bm + (ty << 2) + i;
#pragma unroll
        for (int j = 0; j < 4; j++) {
            int col = bn + (tx << 2) + j;
            g_tmp[m * N + col] = acc[i][j] + bias[col] + R[m * N + col];
        }
    }
}

// ---------------------------------------------------------------------------
// LayerNorm over g_tmp rows -> (outsel ? g_h : g_h1)
// ---------------------------------------------------------------------------
__global__ void ln_k(const float* __restrict__ gam,
                     const float* __restrict__ bet, int outsel) {
    int b = blockIdx.x, tid = threadIdx.x;   // 256 threads, 2 elems each
    float v0 = g_tmp[b * ND + tid];
    float v1 = g_tmp[b * ND + tid + 256];
    __shared__ float sh[8], sh2[8];

    float s = v0 + v1;
#pragma unroll
    for (int o = 16; o; o >>= 1) s += __shfl_xor_sync(0xffffffffu, s, o);
    if ((tid & 31) == 0) sh[tid >> 5] = s;
    __syncthreads();
    float tot = 0.f;
#pragma unroll
    for (int i = 0; i < 8; i++) tot += sh[i];
    float mean = tot * (1.0f / 512.0f);

    float d0 = v0 - mean, d1 = v1 - mean;
    float q = d0 * d0 + d1 * d1;
#pragma unroll
    for (int o = 16; o; o >>= 1) q += __shfl_xor_sync(0xffffffffu, q, o);
    if ((tid & 31) == 0) sh2[tid >> 5] = q;
    __syncthreads();
    float vtot = 0.f;
#pragma unroll
    for (int i = 0; i < 8; i++) vtot += sh2[i];
    float inv = rsqrtf(vtot * (1.0f / 512.0f) + 1e-5f);

    float* out = outsel ? g_h : g_h1;
    out[b * ND + tid]       = d0 * inv * gam[tid]       + bet[tid];
    out[b * ND + tid + 256] = d1 * inv * gam[tid + 256] + bet[tid + 256];
}

// ---------------------------------------------------------------------------
// attention: one warp per (b, h); lane owns head-dims (lane, lane+32).
// Q of new token vs K/V cache positions 0..t. Writes g_att.
// ---------------------------------------------------------------------------
__global__ void attn_k(int t, int l) {
    int wg   = (blockIdx.x << 2) + (threadIdx.x >> 5);  // global warp id
    int lane = threadIdx.x & 31;
    int b = wg >> 3, h = wg & 7;

    const float* qp = g_q + b * ND + h * NHD;
    float q0 = qp[lane], q1 = qp[lane + 32];

    const float* kb = g_kc + (size_t)l * (NB * NH * NT * NHD) + (size_t)(b * NH + h) * NT * NHD;
    const float* vb = g_vc + (size_t)l * (NB * NH * NT * NHD) + (size_t)(b * NH + h) * NT * NHD;

    float sc[NT];
#pragma unroll
    for (int p = 0; p < NT; p++) {
        float s = -1e30f;
        if (p <= t) {
            s = q0 * kb[p * NHD + lane] + q1 * kb[p * NHD + lane + 32];
#pragma unroll
            for (int o = 16; o; o >>= 1) s += __shfl_xor_sync(0xffffffffu, s, o);
            s *= 0.125f;   // 1/sqrt(64)
        }
        sc[p] = s;
    }
    float mx = -1e30f;
#pragma unroll
    for (int p = 0; p < NT; p++) mx = fmaxf(mx, sc[p]);
    float sum = 0.f;
#pragma unroll
    for (int p = 0; p < NT; p++) {
        float e = expf(sc[p] - mx);   // p>t: exp(-1e30) == 0
        sc[p] = e;
        sum += e;
    }
    float invs = 1.0f / sum;
    float o0 = 0.f, o1 = 0.f;
#pragma unroll
    for (int p = 0; p < NT; p++) {
        if (p <= t) {
            float a = sc[p] * invs;
            o0 = fmaf(a, vb[p * NHD + lane],      o0);
            o1 = fmaf(a, vb[p * NHD + lane + 32], o1);
        }
    }
    g_att[b * ND + h * NHD + lane]      = o0;
    g_att[b * ND + h * NHD + lane + 32] = o1;
}

// ---------------------------------------------------------------------------
// head: y[b,c] = g_h[b,:] @ head_w[:,c] + head_b[c]; one warp per output col.
// Writes d_out[b, t, c] and the feedback buffer g_y.
// ---------------------------------------------------------------------------
__global__ void head_k(const float* __restrict__ hw,
                       const float* __restrict__ hb,
                       float* __restrict__ out, int t) {
    int b = blockIdx.x;
    int w = threadIdx.x >> 5;        // 0..2 (96 threads)
    int lane = threadIdx.x & 31;
    float acc = 0.f;
#pragma unroll
    for (int i = 0; i < 16; i++) {
        int d = lane + (i << 5);
        acc = fmaf(g_h[b * ND + d], hw[d * 3 + w], acc);
    }
#pragma unroll
    for (int o = 16; o; o >>= 1) acc += __shfl_xor_sync(0xffffffffu, acc, o);
    if (lane == 0) {
        float v = acc + hb[w];
        out[(b * NT + t) * 3 + w] = v;
        g_y[b * 3 + w] = v;
    }
}

// ---------------------------------------------------------------------------
extern "C" void kernel_launch(void* const* d_in, const int* in_sizes, int n_in,
                              void* d_out, int out_size) {
    const float* x    = (const float*)d_in[0];
    const float* ipw  = (const float*)d_in[1];
    const float* ipb  = (const float*)d_in[2];
    const float* qkvw = (const float*)d_in[3];
    const float* qkvb = (const float*)d_in[4];
    const float* outw = (const float*)d_in[5];
    const float* outb = (const float*)d_in[6];
    const float* ln1s = (const float*)d_in[7];
    const float* ln1b = (const float*)d_in[8];
    const float* ffw1 = (const float*)d_in[9];
    const float* ffb1 = (const float*)d_in[10];
    const float* ffw2 = (const float*)d_in[11];
    const float* ffb2 = (const float*)d_in[12];
    const float* ln2s = (const float*)d_in[13];
    const float* ln2b = (const float*)d_in[14];
    const float* hw   = (const float*)d_in[15];
    const float* hb   = (const float*)d_in[16];
    float* out = (float*)d_out;

    (void)in_sizes; (void)n_in; (void)out_size;

    for (int t = 0; t < NT; t++) {
        embed_k<<<NB, ND>>>(x, ipw, ipb, t);
        for (int l = 0; l < NL; l++) {
            // QKV: 512 x 1536, K=512 -> Q buffer + KV caches at position t
            sgemm64_k<0><<<dim3(3 * ND / 64, NB / 64), 256>>>(
                qkvw + (size_t)l * ND * 3 * ND, qkvb + l * 3 * ND, 3 * ND, ND, l, t);
            // attention over cached positions 0..t
            attn_k<<<NB * NH / 4, 128>>>(t, l);
            // out-proj + bias + residual -> g_tmp
            sgemm32_k<<<dim3(ND / 32, NB / 32), 64>>>(
                outw + (size_t)l * ND * ND, outb + l * ND, ND, 0);
            ln_k<<<NB, 256>>>(ln1s + l * ND, ln1b + l * ND, 0);   // -> g_h1
            // FF1: 512 x 2048 + relu
            sgemm64_k<1><<<dim3(NFF / 64, NB / 64), 256>>>(
                ffw1 + (size_t)l * ND * NFF, ffb1 + l * NFF, NFF, ND, l, t);
            // FF2: K=2048 + bias + residual -> g_tmp
            sgemm32_k<<<dim3(ND / 32, NB / 32), 64>>>(
                ffw2 + (size_t)l * NFF * ND, ffb2 + l * ND, NFF, 1);
            ln_k<<<NB, 256>>>(ln2s + l * ND, ln2b + l * ND, 1);   // -> g_h
        }
        head_k<<<NB, 96>>>(hw, hb, out, t);
    }
}

// round 12
// speedup vs baseline: 1.5189x; 1.5189x over previous
#include <cuda_runtime.h>
#include <math.h>

// ---------------------------------------------------------------------------
// MomentPredictor: 16-step autoregressive rollout of a 2-layer causal
// transformer (B=512, D=512, H=8, FF=2048), exact incremental decoding with
// KV cache. fp32. R12: unified 32x64/128-thread double-buffered GEMM,
// split-K for N=512 GEMMs, fused reduce+bias+residual+LN epilogue.
// ---------------------------------------------------------------------------

#define NB   512   // batch
#define NT   16    // time steps
#define NDIN 7
#define ND   512   // model dim
#define NL   2     // layers
#define NH   8     // heads
#define NHD  64    // head dim
#define NFF  2048

// ---- scratch (device globals: no runtime allocation allowed) ----
__device__ float g_h  [NB * ND];    // current hidden (pre-attn / post-LN2)
__device__ float g_h1 [NB * ND];    // post-LN1 hidden
__device__ float g_q  [NB * ND];    // Q for current token
__device__ float g_att[NB * ND];    // attention output
__device__ float g_ff [NB * NFF];   // FF1 activations
__device__ float g_part[4 * NB * ND];             // split-K partials
__device__ float g_kc [NL * NB * NH * NT * NHD];  // K cache
__device__ float g_vc [NL * NB * NH * NT * NHD];  // V cache
__device__ float g_y  [NB * 3];     // feedback prediction

// ---------------------------------------------------------------------------
// embed: h[b,d] = x_t[b,:] @ ip_w + ip_b + PE(t, d)
// channels 4..6 of x_t come from g_y for t>0 (autoregressive feedback)
// ---------------------------------------------------------------------------
__global__ void embed_k(const float* __restrict__ x,
                        const float* __restrict__ ipw,
                        const float* __restrict__ ipb, int t) {
    int b = blockIdx.x;
    int d = threadIdx.x;            // 512 threads
    float xin[NDIN];
    const float* xr = x + (b * NT + t) * NDIN;
#pragma unroll
    for (int k = 0; k < NDIN; k++) xin[k] = xr[k];
    if (t > 0) {
        xin[4] = g_y[b * 3 + 0];
        xin[5] = g_y[b * 3 + 1];
        xin[6] = g_y[b * 3 + 2];
    }
    float acc = ipb[d];
#pragma unroll
    for (int k = 0; k < NDIN; k++) acc = fmaf(xin[k], ipw[k * ND + d], acc);
    // positional encoding: pe[t, 2i] = sin(t*div_i), pe[t, 2i+1] = cos(t*div_i)
    int   i2  = (d >> 1) << 1;
    float div = expf(-(float)i2 * (9.210340371976184f / 512.0f)); // ln(1e4)/D
    float ang = (float)t * div;
    acc += (d & 1) ? cosf(ang) : sinf(ang);
    g_h[b * ND + d] = acc;
}

// ---------------------------------------------------------------------------
// Unified GEMM: 32(M) x 64(N) tile, 128 threads, 4x4 microtile, BK=16,
// single-sync double-buffered smem.
// MODE 0: QKV (A=g_h,  N=1536, K=512)   -> scatter Q / K-cache / V-cache
// MODE 1: FF1 (A=g_h1, N=2048, K=512)   -> bias + relu -> g_ff
// MODE 2: out-proj partial (A=g_att, N=512, Ksub=256, z=0..1) -> g_part
// MODE 3: FF2 partial      (A=g_ff,  N=512, Ksub=512, z=0..3) -> g_part
// ---------------------------------------------------------------------------
template <int MODE>
__global__ void __launch_bounds__(128) gemm_k(const float* __restrict__ W,
                                              const float* __restrict__ bias,
                                              int N, int lda, int Ksub,
                                              int l, int t) {
    __shared__ __align__(16) float As[2][16][32];
    __shared__ __align__(16) float Bs[2][16][64];

    const float* A = (MODE == 0) ? g_h : (MODE == 1) ? g_h1 :
                     (MODE == 2) ? g_att : g_ff;
    int tid = threadIdx.x;
    int bm = blockIdx.y << 5, bn = blockIdx.x << 6;
    int z  = blockIdx.z;
    int koff = z * Ksub;

    int arow = tid >> 2,  ac4 = (tid & 3) << 2;   // A tile: 32 rows x 16 k
    int brow = tid >> 4,  bc4 = (tid & 15) << 2;  // B tile rows brow, brow+8
    int tx = tid & 15, ty = tid >> 4;

    const float* Aptr = A + (size_t)(bm + arow) * lda + koff + ac4;
    const float* Wptr = W + (size_t)(koff + brow) * N + bn + bc4;

    float acc[4][4];
#pragma unroll
    for (int i = 0; i < 4; i++)
#pragma unroll
        for (int j = 0; j < 4; j++) acc[i][j] = 0.f;

    // prefetch + store tile 0
    float4 av  = *(const float4*)(Aptr);
    float4 bv0 = *(const float4*)(Wptr);
    float4 bv1 = *(const float4*)(Wptr + (size_t)8 * N);
    As[0][ac4 + 0][arow] = av.x;
    As[0][ac4 + 1][arow] = av.y;
    As[0][ac4 + 2][arow] = av.z;
    As[0][ac4 + 3][arow] = av.w;
    *(float4*)&Bs[0][brow][bc4]     = bv0;
    *(float4*)&Bs[0][brow + 8][bc4] = bv1;
    __syncthreads();

    const int nIter = Ksub >> 4;
    int buf = 0;
    for (int it = 0; it < nIter; ++it) {
        if (it + 1 < nIter) {   // prefetch next tile into registers
            av  = *(const float4*)(Aptr + (it + 1) * 16);
            bv0 = *(const float4*)(Wptr + (size_t)((it + 1) * 16)     * N);
            bv1 = *(const float4*)(Wptr + (size_t)((it + 1) * 16 + 8) * N);
        }
#pragma unroll
        for (int k = 0; k < 16; k++) {
            float4 a = *(const float4*)&As[buf][k][ty << 2];
            float4 b = *(const float4*)&Bs[buf][k][tx << 2];
            float ar[4] = {a.x, a.y, a.z, a.w};
            float br[4] = {b.x, b.y, b.z, b.w};
#pragma unroll
            for (int i = 0; i < 4; i++)
#pragma unroll
                for (int j = 0; j < 4; j++)
                    acc[i][j] = fmaf(ar[i], br[j], acc[i][j]);
        }
        if (it + 1 < nIter) {   // store into the other buffer, then publish
            int nb = buf ^ 1;
            As[nb][ac4 + 0][arow] = av.x;
            As[nb][ac4 + 1][arow] = av.y;
            As[nb][ac4 + 2][arow] = av.z;
            As[nb][ac4 + 3][arow] = av.w;
            *(float4*)&Bs[nb][brow][bc4]     = bv0;
            *(float4*)&Bs[nb][brow + 8][bc4] = bv1;
            __syncthreads();
            buf = nb;
        }
    }

#pragma unroll
    for (int i = 0; i < 4; i++) {
        int m = bm + (ty << 2) + i;
#pragma unroll
        for (int j = 0; j < 4; j++) {
            int col = bn + (tx << 2) + j;
            if (MODE == 0) {                 // QKV scatter
                float v = acc[i][j] + bias[col];
                if (col < ND) {
                    g_q[m * ND + col] = v;
                } else if (col < 2 * ND) {
                    int c = col - ND;
                    g_kc[(size_t)l * (NB * NH * NT * NHD) +
                         (size_t)((m * NH + (c >> 6)) * NT + t) * NHD + (c & 63)] = v;
                } else {
                    int c = col - 2 * ND;
                    g_vc[(size_t)l * (NB * NH * NT * NHD) +
                         (size_t)((m * NH + (c >> 6)) * NT + t) * NHD + (c & 63)] = v;
                }
            } else if (MODE == 1) {          // FF1: bias + relu
                g_ff[m * NFF + col] = fmaxf(acc[i][j] + bias[col], 0.f);
            } else {                         // split-K partial (raw)
                g_part[(size_t)z * (NB * ND) + m * ND + col] = acc[i][j];
            }
        }
    }
}

// ---------------------------------------------------------------------------
// Fused split-K reduce + bias + residual + LayerNorm.
// outsel 0: resid=g_h,  out=g_h1 (after out-proj);  nsplit=2
// outsel 1: resid=g_h1, out=g_h  (after FF2);       nsplit=4
// ---------------------------------------------------------------------------
__global__ void redln_k(const float* __restrict__ bias,
                        const float* __restrict__ gam,
                        const float* __restrict__ bet,
                        int nsplit, int outsel) {
    int b = blockIdx.x, tid = threadIdx.x;   // 256 threads, 2 cols each
    const float* R = outsel ? g_h1 : g_h;
    float v0 = R[b * ND + tid]       + bias[tid];
    float v1 = R[b * ND + tid + 256] + bias[tid + 256];
#pragma unroll 4
    for (int z = 0; z < nsplit; z++) {
        v0 += g_part[(size_t)z * (NB * ND) + b * ND + tid];
        v1 += g_part[(size_t)z * (NB * ND) + b * ND + tid + 256];
    }

    __shared__ float sh[8], sh2[8];
    float s = v0 + v1;
#pragma unroll
    for (int o = 16; o; o >>= 1) s += __shfl_xor_sync(0xffffffffu, s, o);
    if ((tid & 31) == 0) sh[tid >> 5] = s;
    __syncthreads();
    float tot = 0.f;
#pragma unroll
    for (int i = 0; i < 8; i++) tot += sh[i];
    float mean = tot * (1.0f / 512.0f);

    float d0 = v0 - mean, d1 = v1 - mean;
    float q = d0 * d0 + d1 * d1;
#pragma unroll
    for (int o = 16; o; o >>= 1) q += __shfl_xor_sync(0xffffffffu, q, o);
    if ((tid & 31) == 0) sh2[tid >> 5] = q;
    __syncthreads();
    float vtot = 0.f;
#pragma unroll
    for (int i = 0; i < 8; i++) vtot += sh2[i];
    float inv = rsqrtf(vtot * (1.0f / 512.0f) + 1e-5f);

    float* out = outsel ? g_h : g_h1;
    out[b * ND + tid]       = d0 * inv * gam[tid]       + bet[tid];
    out[b * ND + tid + 256] = d1 * inv * gam[tid + 256] + bet[tid + 256];
}

// ---------------------------------------------------------------------------
// attention: one warp per (b, h); lane owns head-dims (lane, lane+32).
// ---------------------------------------------------------------------------
__global__ void attn_k(int t, int l) {
    int wg   = (blockIdx.x << 2) + (threadIdx.x >> 5);
    int lane = threadIdx.x & 31;
    int b = wg >> 3, h = wg & 7;

    const float* qp = g_q + b * ND + h * NHD;
    float q0 = qp[lane], q1 = qp[lane + 32];

    const float* kb = g_kc + (size_t)l * (NB * NH * NT * NHD) + (size_t)(b * NH + h) * NT * NHD;
    const float* vb = g_vc + (size_t)l * (NB * NH * NT * NHD) + (size_t)(b * NH + h) * NT * NHD;

    float sc[NT];
#pragma unroll
    for (int p = 0; p < NT; p++) {
        float s = -1e30f;
        if (p <= t) {
            s = q0 * kb[p * NHD + lane] + q1 * kb[p * NHD + lane + 32];
#pragma unroll
            for (int o = 16; o; o >>= 1) s += __shfl_xor_sync(0xffffffffu, s, o);
            s *= 0.125f;   // 1/sqrt(64)
        }
        sc[p] = s;
    }
    float mx = -1e30f;
#pragma unroll
    for (int p = 0; p < NT; p++) mx = fmaxf(mx, sc[p]);
    float sum = 0.f;
#pragma unroll
    for (int p = 0; p < NT; p++) {
        float e = expf(sc[p] - mx);
        sc[p] = e;
        sum += e;
    }
    float invs = 1.0f / sum;
    float o0 = 0.f, o1 = 0.f;
#pragma unroll
    for (int p = 0; p < NT; p++) {
        if (p <= t) {
            float a = sc[p] * invs;
            o0 = fmaf(a, vb[p * NHD + lane],      o0);
            o1 = fmaf(a, vb[p * NHD + lane + 32], o1);
        }
    }
    g_att[b * ND + h * NHD + lane]      = o0;
    g_att[b * ND + h * NHD + lane + 32] = o1;
}

// ---------------------------------------------------------------------------
// head: y[b,c] = g_h[b,:] @ head_w[:,c] + head_b[c]
// ---------------------------------------------------------------------------
__global__ void head_k(const float* __restrict__ hw,
                       const float* __restrict__ hb,
                       float* __restrict__ out, int t) {
    int b = blockIdx.x;
    int w = threadIdx.x >> 5;        // 0..2 (96 threads)
    int lane = threadIdx.x & 31;
    float acc = 0.f;
#pragma unroll
    for (int i = 0; i < 16; i++) {
        int d = lane + (i << 5);
        acc = fmaf(g_h[b * ND + d], hw[d * 3 + w], acc);
    }
#pragma unroll
    for (int o = 16; o; o >>= 1) acc += __shfl_xor_sync(0xffffffffu, acc, o);
    if (lane == 0) {
        float v = acc + hb[w];
        out[(b * NT + t) * 3 + w] = v;
        g_y[b * 3 + w] = v;
    }
}

// ---------------------------------------------------------------------------
extern "C" void kernel_launch(void* const* d_in, const int* in_sizes, int n_in,
                              void* d_out, int out_size) {
    const float* x    = (const float*)d_in[0];
    const float* ipw  = (const float*)d_in[1];
    const float* ipb  = (const float*)d_in[2];
    const float* qkvw = (const float*)d_in[3];
    const float* qkvb = (const float*)d_in[4];
    const float* outw = (const float*)d_in[5];
    const float* outb = (const float*)d_in[6];
    const float* ln1s = (const float*)d_in[7];
    const float* ln1b = (const float*)d_in[8];
    const float* ffw1 = (const float*)d_in[9];
    const float* ffb1 = (const float*)d_in[10];
    const float* ffw2 = (const float*)d_in[11];
    const float* ffb2 = (const float*)d_in[12];
    const float* ln2s = (const float*)d_in[13];
    const float* ln2b = (const float*)d_in[14];
    const float* hw   = (const float*)d_in[15];
    const float* hb   = (const float*)d_in[16];
    float* out = (float*)d_out;

    (void)in_sizes; (void)n_in; (void)out_size;

    for (int t = 0; t < NT; t++) {
        embed_k<<<NB, ND>>>(x, ipw, ipb, t);
        for (int l = 0; l < NL; l++) {
            // QKV: (512 x 512) @ (512 x 1536) -> Q buffer + KV cache at pos t
            gemm_k<0><<<dim3(3 * ND / 64, NB / 32, 1), 128>>>(
                qkvw + (size_t)l * ND * 3 * ND, qkvb + l * 3 * ND,
                3 * ND, ND, ND, l, t);
            // attention over cached positions 0..t
            attn_k<<<NB * NH / 4, 128>>>(t, l);
            // out-proj partials: K=512 split 2
            gemm_k<2><<<dim3(ND / 64, NB / 32, 2), 128>>>(
                outw + (size_t)l * ND * ND, outb + l * ND,
                ND, ND, ND / 2, l, t);
            // reduce + bias + residual(g_h) + LN1 -> g_h1
            redln_k<<<NB, 256>>>(outb + l * ND, ln1s + l * ND, ln1b + l * ND, 2, 0);
            // FF1: (512 x 512) @ (512 x 2048), bias + relu -> g_ff
            gemm_k<1><<<dim3(NFF / 64, NB / 32, 1), 128>>>(
                ffw1 + (size_t)l * ND * NFF, ffb1 + l * NFF,
                NFF, ND, ND, l, t);
            // FF2 partials: K=2048 split 4
            gemm_k<3><<<dim3(ND / 64, NB / 32, 4), 128>>>(
                ffw2 + (size_t)l * NFF * ND, ffb2 + l * ND,
                ND, NFF, NFF / 4, l, t);
            // reduce + bias + residual(g_h1) + LN2 -> g_h
            redln_k<<<NB, 256>>>(ffb2 + l * ND, ln2s + l * ND, ln2b + l * ND, 4, 1);
        }
        head_k<<<NB, 96>>>(hw, hb, out, t);
    }
}

// round 13
// speedup vs baseline: 1.5417x; 1.0150x over previous
#include <cuda_runtime.h>
#include <math.h>

// ---------------------------------------------------------------------------
// MomentPredictor: 16-step autoregressive rollout of a 2-layer causal
// transformer (B=512, D=512, H=8, FF=2048), exact incremental decoding with
// KV cache. fp32. R13: BK=32 double-buffered GEMM with register-pipelined
// fragments, deeper split-K (out-proj x4, FF2 x8) to raise warps/SM.
// ---------------------------------------------------------------------------

#define NB   512   // batch
#define NT   16    // time steps
#define NDIN 7
#define ND   512   // model dim
#define NL   2     // layers
#define NH   8     // heads
#define NHD  64    // head dim
#define NFF  2048

// ---- scratch (device globals: no runtime allocation allowed) ----
__device__ float g_h  [NB * ND];    // current hidden (pre-attn / post-LN2)
__device__ float g_h1 [NB * ND];    // post-LN1 hidden
__device__ float g_q  [NB * ND];    // Q for current token
__device__ float g_att[NB * ND];    // attention output
__device__ float g_ff [NB * NFF];   // FF1 activations
__device__ float g_part[8 * NB * ND];             // split-K partials
__device__ float g_kc [NL * NB * NH * NT * NHD];  // K cache
__device__ float g_vc [NL * NB * NH * NT * NHD];  // V cache
__device__ float g_y  [NB * 3];     // feedback prediction

// ---------------------------------------------------------------------------
// embed: h[b,d] = x_t[b,:] @ ip_w + ip_b + PE(t, d)
// ---------------------------------------------------------------------------
__global__ void embed_k(const float* __restrict__ x,
                        const float* __restrict__ ipw,
                        const float* __restrict__ ipb, int t) {
    int b = blockIdx.x;
    int d = threadIdx.x;            // 512 threads
    float xin[NDIN];
    const float* xr = x + (b * NT + t) * NDIN;
#pragma unroll
    for (int k = 0; k < NDIN; k++) xin[k] = xr[k];
    if (t > 0) {
        xin[4] = g_y[b * 3 + 0];
        xin[5] = g_y[b * 3 + 1];
        xin[6] = g_y[b * 3 + 2];
    }
    float acc = ipb[d];
#pragma unroll
    for (int k = 0; k < NDIN; k++) acc = fmaf(xin[k], ipw[k * ND + d], acc);
    int   i2  = (d >> 1) << 1;
    float div = expf(-(float)i2 * (9.210340371976184f / 512.0f)); // ln(1e4)/D
    float ang = (float)t * div;
    acc += (d & 1) ? cosf(ang) : sinf(ang);
    g_h[b * ND + d] = acc;
}

// ---------------------------------------------------------------------------
// Unified GEMM: 32(M) x 64(N) tile, 128 threads, 4x4 microtile, BK=32,
// double-buffered smem + register-pipelined fragments.
// MODE 0: QKV (A=g_h,  N=1536, K=512)   -> scatter Q / K-cache / V-cache
// MODE 1: FF1 (A=g_h1, N=2048, K=512)   -> bias + relu -> g_ff
// MODE 2: out-proj partial (A=g_att, N=512, Ksub=128, z=0..3) -> g_part
// MODE 3: FF2 partial      (A=g_ff,  N=512, Ksub=256, z=0..7) -> g_part
// ---------------------------------------------------------------------------
template <int MODE>
__global__ void __launch_bounds__(128) gemm_k(const float* __restrict__ W,
                                              const float* __restrict__ bias,
                                              int N, int lda, int Ksub,
                                              int l, int t) {
    __shared__ __align__(16) float As[2][32][32];
    __shared__ __align__(16) float Bs[2][32][64];

    const float* A = (MODE == 0) ? g_h : (MODE == 1) ? g_h1 :
                     (MODE == 2) ? g_att : g_ff;
    int tid = threadIdx.x;
    int bm = blockIdx.y << 5, bn = blockIdx.x << 6;
    int z  = blockIdx.z;
    int koff = z * Ksub;

    int tx = tid & 15, ty = tid >> 4;

    // A tile (32 m x 32 k): 2 float4 per thread
    int arow = tid >> 3;                // 0..15 (r adds +16)
    int ac4  = (tid & 7) << 2;          // 0..28
    // B tile (32 k x 64 n): 4 float4 per thread
    int brow = tid >> 4;                // 0..7 (r adds +8)
    int bc4  = (tid & 15) << 2;

    const float* Aptr0 = A + (size_t)(bm + arow)      * lda + koff + ac4;
    const float* Aptr1 = A + (size_t)(bm + arow + 16) * lda + koff + ac4;
    const float* Wptr  = W + (size_t)(koff + brow) * N + bn + bc4;

    float acc[4][4];
#pragma unroll
    for (int i = 0; i < 4; i++)
#pragma unroll
        for (int j = 0; j < 4; j++) acc[i][j] = 0.f;

    // ---- prefetch + store tile 0 ----
    float4 pa0 = *(const float4*)(Aptr0);
    float4 pa1 = *(const float4*)(Aptr1);
    float4 pb[4];
#pragma unroll
    for (int r = 0; r < 4; r++)
        pb[r] = *(const float4*)(Wptr + (size_t)(r * 8) * N);

    {
        As[0][ac4 + 0][arow] = pa0.x;  As[0][ac4 + 1][arow] = pa0.y;
        As[0][ac4 + 2][arow] = pa0.z;  As[0][ac4 + 3][arow] = pa0.w;
        As[0][ac4 + 0][arow + 16] = pa1.x;  As[0][ac4 + 1][arow + 16] = pa1.y;
        As[0][ac4 + 2][arow + 16] = pa1.z;  As[0][ac4 + 3][arow + 16] = pa1.w;
#pragma unroll
        for (int r = 0; r < 4; r++)
            *(float4*)&Bs[0][brow + r * 8][bc4] = pb[r];
    }
    __syncthreads();

    const int nIter = Ksub >> 5;
    int buf = 0;
    for (int it = 0; it < nIter; ++it) {
        if (it + 1 < nIter) {   // prefetch next tile into registers
            int kt = (it + 1) << 5;
            pa0 = *(const float4*)(Aptr0 + kt);
            pa1 = *(const float4*)(Aptr1 + kt);
#pragma unroll
            for (int r = 0; r < 4; r++)
                pb[r] = *(const float4*)(Wptr + (size_t)(kt + r * 8) * N);
        }
        // register-pipelined compute over 32 k-steps
        float4 acur = *(const float4*)&As[buf][0][ty << 2];
        float4 bcur = *(const float4*)&Bs[buf][0][tx << 2];
#pragma unroll
        for (int k = 0; k < 32; k++) {
            float4 anxt, bnxt;
            if (k < 31) {
                anxt = *(const float4*)&As[buf][k + 1][ty << 2];
                bnxt = *(const float4*)&Bs[buf][k + 1][tx << 2];
            }
            float ar[4] = {acur.x, acur.y, acur.z, acur.w};
            float br[4] = {bcur.x, bcur.y, bcur.z, bcur.w};
#pragma unroll
            for (int i = 0; i < 4; i++)
#pragma unroll
                for (int j = 0; j < 4; j++)
                    acc[i][j] = fmaf(ar[i], br[j], acc[i][j]);
            if (k < 31) { acur = anxt; bcur = bnxt; }
        }
        if (it + 1 < nIter) {   // store into the other buffer, then publish
            int nb = buf ^ 1;
            As[nb][ac4 + 0][arow] = pa0.x;  As[nb][ac4 + 1][arow] = pa0.y;
            As[nb][ac4 + 2][arow] = pa0.z;  As[nb][ac4 + 3][arow] = pa0.w;
            As[nb][ac4 + 0][arow + 16] = pa1.x;  As[nb][ac4 + 1][arow + 16] = pa1.y;
            As[nb][ac4 + 2][arow + 16] = pa1.z;  As[nb][ac4 + 3][arow + 16] = pa1.w;
#pragma unroll
            for (int r = 0; r < 4; r++)
                *(float4*)&Bs[nb][brow + r * 8][bc4] = pb[r];
            __syncthreads();
            buf = nb;
        }
    }

#pragma unroll
    for (int i = 0; i < 4; i++) {
        int m = bm + (ty << 2) + i;
#pragma unroll
        for (int j = 0; j < 4; j++) {
            int col = bn + (tx << 2) + j;
            if (MODE == 0) {                 // QKV scatter
                float v = acc[i][j] + bias[col];
                if (col < ND) {
                    g_q[m * ND + col] = v;
                } else if (col < 2 * ND) {
                    int c = col - ND;
                    g_kc[(size_t)l * (NB * NH * NT * NHD) +
                         (size_t)((m * NH + (c >> 6)) * NT + t) * NHD + (c & 63)] = v;
                } else {
                    int c = col - 2 * ND;
                    g_vc[(size_t)l * (NB * NH * NT * NHD) +
                         (size_t)((m * NH + (c >> 6)) * NT + t) * NHD + (c & 63)] = v;
                }
            } else if (MODE == 1) {          // FF1: bias + relu
                g_ff[m * NFF + col] = fmaxf(acc[i][j] + bias[col], 0.f);
            } else {                         // split-K partial (raw)
                g_part[(size_t)z * (NB * ND) + m * ND + col] = acc[i][j];
            }
        }
    }
}

// ---------------------------------------------------------------------------
// Fused split-K reduce + bias + residual + LayerNorm.
// outsel 0: resid=g_h,  out=g_h1 (after out-proj)
// outsel 1: resid=g_h1, out=g_h  (after FF2)
// ---------------------------------------------------------------------------
__global__ void redln_k(const float* __restrict__ bias,
                        const float* __restrict__ gam,
                        const float* __restrict__ bet,
                        int nsplit, int outsel) {
    int b = blockIdx.x, tid = threadIdx.x;   // 256 threads, 2 cols each
    const float* R = outsel ? g_h1 : g_h;
    float v0 = R[b * ND + tid]       + bias[tid];
    float v1 = R[b * ND + tid + 256] + bias[tid + 256];
    for (int z = 0; z < nsplit; z++) {
        v0 += g_part[(size_t)z * (NB * ND) + b * ND + tid];
        v1 += g_part[(size_t)z * (NB * ND) + b * ND + tid + 256];
    }

    __shared__ float sh[8], sh2[8];
    float s = v0 + v1;
#pragma unroll
    for (int o = 16; o; o >>= 1) s += __shfl_xor_sync(0xffffffffu, s, o);
    if ((tid & 31) == 0) sh[tid >> 5] = s;
    __syncthreads();
    float tot = 0.f;
#pragma unroll
    for (int i = 0; i < 8; i++) tot += sh[i];
    float mean = tot * (1.0f / 512.0f);

    float d0 = v0 - mean, d1 = v1 - mean;
    float q = d0 * d0 + d1 * d1;
#pragma unroll
    for (int o = 16; o; o >>= 1) q += __shfl_xor_sync(0xffffffffu, q, o);
    if ((tid & 31) == 0) sh2[tid >> 5] = q;
    __syncthreads();
    float vtot = 0.f;
#pragma unroll
    for (int i = 0; i < 8; i++) vtot += sh2[i];
    float inv = rsqrtf(vtot * (1.0f / 512.0f) + 1e-5f);

    float* out = outsel ? g_h : g_h1;
    out[b * ND + tid]       = d0 * inv * gam[tid]       + bet[tid];
    out[b * ND + tid + 256] = d1 * inv * gam[tid + 256] + bet[tid + 256];
}

// ---------------------------------------------------------------------------
// attention: one warp per (b, h); lane owns head-dims (lane, lane+32).
// ---------------------------------------------------------------------------
__global__ void attn_k(int t, int l) {
    int wg   = (blockIdx.x << 2) + (threadIdx.x >> 5);
    int lane = threadIdx.x & 31;
    int b = wg >> 3, h = wg & 7;

    const float* qp = g_q + b * ND + h * NHD;
    float q0 = qp[lane], q1 = qp[lane + 32];

    const float* kb = g_kc + (size_t)l * (NB * NH * NT * NHD) + (size_t)(b * NH + h) * NT * NHD;
    const float* vb = g_vc + (size_t)l * (NB * NH * NT * NHD) + (size_t)(b * NH + h) * NT * NHD;

    float sc[NT];
#pragma unroll
    for (int p = 0; p < NT; p++) {
        float s = -1e30f;
        if (p <= t) {
            s = q0 * kb[p * NHD + lane] + q1 * kb[p * NHD + lane + 32];
#pragma unroll
            for (int o = 16; o; o >>= 1) s += __shfl_xor_sync(0xffffffffu, s, o);
            s *= 0.125f;   // 1/sqrt(64)
        }
        sc[p] = s;
    }
    float mx = -1e30f;
#pragma unroll
    for (int p = 0; p < NT; p++) mx = fmaxf(mx, sc[p]);
    float sum = 0.f;
#pragma unroll
    for (int p = 0; p < NT; p++) {
        float e = expf(sc[p] - mx);
        sc[p] = e;
        sum += e;
    }
    float invs = 1.0f / sum;
    float o0 = 0.f, o1 = 0.f;
#pragma unroll
    for (int p = 0; p < NT; p++) {
        if (p <= t) {
            float a = sc[p] * invs;
            o0 = fmaf(a, vb[p * NHD + lane],      o0);
            o1 = fmaf(a, vb[p * NHD + lane + 32], o1);
        }
    }
    g_att[b * ND + h * NHD + lane]      = o0;
    g_att[b * ND + h * NHD + lane + 32] = o1;
}

// ---------------------------------------------------------------------------
// head: y[b,c] = g_h[b,:] @ head_w[:,c] + head_b[c]
// ---------------------------------------------------------------------------
__global__ void head_k(const float* __restrict__ hw,
                       const float* __restrict__ hb,
                       float* __restrict__ out, int t) {
    int b = blockIdx.x;
    int w = threadIdx.x >> 5;        // 0..2 (96 threads)
    int lane = threadIdx.x & 31;
    float acc = 0.f;
#pragma unroll
    for (int i = 0; i < 16; i++) {
        int d = lane + (i << 5);
        acc = fmaf(g_h[b * ND + d], hw[d * 3 + w], acc);
    }
#pragma unroll
    for (int o = 16; o; o >>= 1) acc += __shfl_xor_sync(0xffffffffu, acc, o);
    if (lane == 0) {
        float v = acc + hb[w];
        out[(b * NT + t) * 3 + w] = v;
        g_y[b * 3 + w] = v;
    }
}

// ---------------------------------------------------------------------------
extern "C" void kernel_launch(void* const* d_in, const int* in_sizes, int n_in,
                              void* d_out, int out_size) {
    const float* x    = (const float*)d_in[0];
    const float* ipw  = (const float*)d_in[1];
    const float* ipb  = (const float*)d_in[2];
    const float* qkvw = (const float*)d_in[3];
    const float* qkvb = (const float*)d_in[4];
    const float* outw = (const float*)d_in[5];
    const float* outb = (const float*)d_in[6];
    const float* ln1s = (const float*)d_in[7];
    const float* ln1b = (const float*)d_in[8];
    const float* ffw1 = (const float*)d_in[9];
    const float* ffb1 = (const float*)d_in[10];
    const float* ffw2 = (const float*)d_in[11];
    const float* ffb2 = (const float*)d_in[12];
    const float* ln2s = (const float*)d_in[13];
    const float* ln2b = (const float*)d_in[14];
    const float* hw   = (const float*)d_in[15];
    const float* hb   = (const float*)d_in[16];
    float* out = (float*)d_out;

    (void)in_sizes; (void)n_in; (void)out_size;

    for (int t = 0; t < NT; t++) {
        embed_k<<<NB, ND>>>(x, ipw, ipb, t);
        for (int l = 0; l < NL; l++) {
            // QKV: (512 x 512) @ (512 x 1536) -> Q buffer + KV cache at pos t
            gemm_k<0><<<dim3(3 * ND / 64, NB / 32, 1), 128>>>(
                qkvw + (size_t)l * ND * 3 * ND, qkvb + l * 3 * ND,
                3 * ND, ND, ND, l, t);
            // attention over cached positions 0..t
            attn_k<<<NB * NH / 4, 128>>>(t, l);
            // out-proj partials: K=512 split 4
            gemm_k<2><<<dim3(ND / 64, NB / 32, 4), 128>>>(
                outw + (size_t)l * ND * ND, outb + l * ND,
                ND, ND, ND / 4, l, t);
            // reduce + bias + residual(g_h) + LN1 -> g_h1
            redln_k<<<NB, 256>>>(outb + l * ND, ln1s + l * ND, ln1b + l * ND, 4, 0);
            // FF1: (512 x 512) @ (512 x 2048), bias + relu -> g_ff
            gemm_k<1><<<dim3(NFF / 64, NB / 32, 1), 128>>>(
                ffw1 + (size_t)l * ND * NFF, ffb1 + l * NFF,
                NFF, ND, ND, l, t);
            // FF2 partials: K=2048 split 8
            gemm_k<3><<<dim3(ND / 64, NB / 32, 8), 128>>>(
                ffw2 + (size_t)l * NFF * ND, ffb2 + l * ND,
                ND, NFF, NFF / 8, l, t);
            // reduce + bias + residual(g_h1) + LN2 -> g_h
            redln_k<<<NB, 256>>>(ffb2 + l * ND, ln2s + l * ND, ln2b + l * ND, 8, 1);
        }
        head_k<<<NB, 96>>>(hw, hb, out, t);
    }
}

// round 16
// speedup vs baseline: 2.5106x; 1.6284x over previous
#include <cuda_runtime.h>
#include <cuda_bf16.h>
#include <math.h>

// ---------------------------------------------------------------------------
// MomentPredictor: 16-step autoregressive rollout of a 2-layer causal
// transformer (B=512, D=512, H=8, FF=2048), exact incremental decoding with
// KV cache. R16: R15 (mma.sync bf16 m16n8k16, bf16-split 3-pass) with the
// smem loader fixed to cover the full 64x32 tile (R15 loaded half -> NaN).
// ---------------------------------------------------------------------------

#define NB   512
#define NT   16
#define NDIN 7
#define ND   512
#define NL   2
#define NH   8
#define NHD  64
#define NFF  2048

typedef __nv_bfloat16 bf16;

// ---- scratch (device globals) ----
__device__ float g_h  [NB * ND];
__device__ float g_h1 [NB * ND];
__device__ float g_q  [NB * ND];
__device__ float g_part[4 * NB * ND];
__device__ float g_kc [NL * NB * NH * NT * NHD];
__device__ float g_vc [NL * NB * NH * NT * NHD];
__device__ float g_y  [NB * 3];

// activation bf16 hi/lo mirrors (GEMM A operands)
__device__ __align__(16) bf16 gh_hi [NB * ND],  gh_lo [NB * ND];
__device__ __align__(16) bf16 gh1_hi[NB * ND],  gh1_lo[NB * ND];
__device__ __align__(16) bf16 gat_hi[NB * ND],  gat_lo[NB * ND];
__device__ __align__(16) bf16 gff_hi[NB * NFF], gff_lo[NB * NFF];

// transposed+split weights [N, K] K-major bf16
__device__ __align__(16) bf16 wqkv_hi[NL * 3 * ND * ND], wqkv_lo[NL * 3 * ND * ND];
__device__ __align__(16) bf16 wout_hi[NL * ND * ND],     wout_lo[NL * ND * ND];
__device__ __align__(16) bf16 wff1_hi[NL * NFF * ND],    wff1_lo[NL * NFF * ND];
__device__ __align__(16) bf16 wff2_hi[NL * ND * NFF],    wff2_lo[NL * ND * NFF];

__device__ __forceinline__ void split_store(float v, bf16* hi, bf16* lo, int idx) {
    bf16 h = __float2bfloat16(v);
    hi[idx] = h;
    lo[idx] = __float2bfloat16(v - __bfloat162float(h));
}

// m16n8k16 row.col bf16 -> f32 accumulate
__device__ __forceinline__ void mma_bf16(float* d, const unsigned* a, const unsigned* b) {
    asm volatile(
        "mma.sync.aligned.m16n8k16.row.col.f32.bf16.bf16.f32 "
        "{%0,%1,%2,%3}, {%4,%5,%6,%7}, {%8,%9}, {%0,%1,%2,%3};"
        : "+f"(d[0]), "+f"(d[1]), "+f"(d[2]), "+f"(d[3])
        : "r"(a[0]), "r"(a[1]), "r"(a[2]), "r"(a[3]), "r"(b[0]), "r"(b[1]));
}

// ---------------------------------------------------------------------------
// weight transpose + bf16 split: src [K,N] fp32 -> dst [N,K] bf16 hi/lo
// ---------------------------------------------------------------------------
__global__ void wsplit_k(const float* __restrict__ src,
                         bf16* __restrict__ dhi, bf16* __restrict__ dlo,
                         int K, int N) {
    __shared__ float tile[32][33];
    int nb = blockIdx.x << 5, kb = blockIdx.y << 5;
    int tx = threadIdx.x, ty = threadIdx.y;   // 32 x 8
#pragma unroll
    for (int j = 0; j < 32; j += 8)
        tile[ty + j][tx] = src[(size_t)(kb + ty + j) * N + nb + tx];
    __syncthreads();
#pragma unroll
    for (int j = 0; j < 32; j += 8) {
        float v = tile[tx][ty + j];
        bf16 h = __float2bfloat16(v);
        size_t o = (size_t)(nb + ty + j) * K + kb + tx;
        dhi[o] = h;
        dlo[o] = __float2bfloat16(v - __bfloat162float(h));
    }
}

// ---------------------------------------------------------------------------
// embed: h[b,d] = x_t[b,:] @ ip_w + ip_b + PE(t,d); writes fp32 + mirrors
// ---------------------------------------------------------------------------
__global__ void embed_k(const float* __restrict__ x,
                        const float* __restrict__ ipw,
                        const float* __restrict__ ipb, int t) {
    int b = blockIdx.x;
    int d = threadIdx.x;            // 512 threads
    float xin[NDIN];
    const float* xr = x + (b * NT + t) * NDIN;
#pragma unroll
    for (int k = 0; k < NDIN; k++) xin[k] = xr[k];
    if (t > 0) {
        xin[4] = g_y[b * 3 + 0];
        xin[5] = g_y[b * 3 + 1];
        xin[6] = g_y[b * 3 + 2];
    }
    float acc = ipb[d];
#pragma unroll
    for (int k = 0; k < NDIN; k++) acc = fmaf(xin[k], ipw[k * ND + d], acc);
    int   i2  = (d >> 1) << 1;
    float div = expf(-(float)i2 * (9.210340371976184f / 512.0f));
    float ang = (float)t * div;
    acc += (d & 1) ? cosf(ang) : sinf(ang);
    g_h[b * ND + d] = acc;
    split_store(acc, gh_hi, gh_lo, b * ND + d);
}

// ---------------------------------------------------------------------------
// Tensor-pipe GEMM: 64(M) x 64(N) tile, 128 threads (2x2 warps, each 32x32
// via 2x4 m16n8k16 frags), BK=32, double-buffered smem, bf16-split 3-pass.
// MODE 0: QKV (A=gh,  N=1536, K=512)  -> Q fp32 / KV caches fp32
// MODE 1: FF1 (A=gh1, N=2048, K=512)  -> bias+relu -> gff mirrors
// MODE 2: out-proj partial (A=gat, z splits) -> g_part
// MODE 3: FF2 partial      (A=gff, z splits) -> g_part
// ---------------------------------------------------------------------------
template <int MODE>
__global__ void __launch_bounds__(128) gemmM_k(const bf16* __restrict__ Whi,
                                               const bf16* __restrict__ Wlo,
                                               const float* __restrict__ bias,
                                               int lda, int Ksub, int l, int t) {
    __shared__ __align__(16) bf16 Ahs[2][64][40];
    __shared__ __align__(16) bf16 Als[2][64][40];
    __shared__ __align__(16) bf16 Bhs[2][64][40];
    __shared__ __align__(16) bf16 Bls[2][64][40];

    const bf16 *Ahi_g, *Alo_g;
    if (MODE == 0)      { Ahi_g = gh_hi;  Alo_g = gh_lo;  }
    else if (MODE == 1) { Ahi_g = gh1_hi; Alo_g = gh1_lo; }
    else if (MODE == 2) { Ahi_g = gat_hi; Alo_g = gat_lo; }
    else                { Ahi_g = gff_hi; Alo_g = gff_lo; }

    int tid = threadIdx.x, lane = tid & 31, warp = tid >> 5;
    int wm = warp >> 1, wn = warp & 1;          // 2x2 warp grid
    int bm = blockIdx.y << 6, bn = blockIdx.x << 6, z = blockIdx.z;
    int koff = z * Ksub;

    // loader: full 64x32 tile coverage — rows (lrow, lrow+32), 8 bf16 per ld
    int lrow = tid >> 2, lcol = (tid & 3) << 3;

    float d[2][4][4];
#pragma unroll
    for (int mi = 0; mi < 2; mi++)
#pragma unroll
        for (int nj = 0; nj < 4; nj++)
#pragma unroll
            for (int e = 0; e < 4; e++) d[mi][nj][e] = 0.f;

    const bf16* Ah_p = Ahi_g + (size_t)(bm + lrow) * lda + koff + lcol;
    const bf16* Al_p = Alo_g + (size_t)(bm + lrow) * lda + koff + lcol;
    const bf16* Bh_p = Whi   + (size_t)(bn + lrow) * lda + koff + lcol;
    const bf16* Bl_p = Wlo   + (size_t)(bn + lrow) * lda + koff + lcol;
    const size_t rstep = (size_t)32 * lda;      // +32 rows

    // chunk 0 into buffer 0
    *(uint4*)&Ahs[0][lrow     ][lcol] = *(const uint4*)(Ah_p);
    *(uint4*)&Ahs[0][lrow + 32][lcol] = *(const uint4*)(Ah_p + rstep);
    *(uint4*)&Als[0][lrow     ][lcol] = *(const uint4*)(Al_p);
    *(uint4*)&Als[0][lrow + 32][lcol] = *(const uint4*)(Al_p + rstep);
    *(uint4*)&Bhs[0][lrow     ][lcol] = *(const uint4*)(Bh_p);
    *(uint4*)&Bhs[0][lrow + 32][lcol] = *(const uint4*)(Bh_p + rstep);
    *(uint4*)&Bls[0][lrow     ][lcol] = *(const uint4*)(Bl_p);
    *(uint4*)&Bls[0][lrow + 32][lcol] = *(const uint4*)(Bl_p + rstep);
    __syncthreads();

    const int nCh = Ksub >> 5;
    int g = lane >> 2, c2 = (lane & 3) << 1;
    for (int c = 0; c < nCh; ++c) {
        int buf = c & 1;
        uint4 pf[8];
        if (c + 1 < nCh) {      // prefetch next chunk into registers
            int ko = (c + 1) << 5;
            pf[0] = *(const uint4*)(Ah_p + ko);
            pf[1] = *(const uint4*)(Ah_p + rstep + ko);
            pf[2] = *(const uint4*)(Al_p + ko);
            pf[3] = *(const uint4*)(Al_p + rstep + ko);
            pf[4] = *(const uint4*)(Bh_p + ko);
            pf[5] = *(const uint4*)(Bh_p + rstep + ko);
            pf[6] = *(const uint4*)(Bl_p + ko);
            pf[7] = *(const uint4*)(Bl_p + rstep + ko);
        }
#pragma unroll
        for (int ks = 0; ks < 2; ks++) {
            int kb = ks << 4;
            unsigned ah[2][4], al[2][4], bh[4][2], bl[4][2];
#pragma unroll
            for (int mi = 0; mi < 2; mi++) {
                int r = wm * 32 + mi * 16 + g;
                // PTX m16n8k16 A frag: a0=(g, klo) a1=(g+8, klo) a2=(g, khi) a3=(g+8, khi)
                ah[mi][0] = *(const unsigned*)&Ahs[buf][r    ][kb + c2];
                ah[mi][1] = *(const unsigned*)&Ahs[buf][r + 8][kb + c2];
                ah[mi][2] = *(const unsigned*)&Ahs[buf][r    ][kb + c2 + 8];
                ah[mi][3] = *(const unsigned*)&Ahs[buf][r + 8][kb + c2 + 8];
                al[mi][0] = *(const unsigned*)&Als[buf][r    ][kb + c2];
                al[mi][1] = *(const unsigned*)&Als[buf][r + 8][kb + c2];
                al[mi][2] = *(const unsigned*)&Als[buf][r    ][kb + c2 + 8];
                al[mi][3] = *(const unsigned*)&Als[buf][r + 8][kb + c2 + 8];
            }
#pragma unroll
            for (int nj = 0; nj < 4; nj++) {
                int n = wn * 32 + nj * 8 + g;
                bh[nj][0] = *(const unsigned*)&Bhs[buf][n][kb + c2];
                bh[nj][1] = *(const unsigned*)&Bhs[buf][n][kb + c2 + 8];
                bl[nj][0] = *(const unsigned*)&Bls[buf][n][kb + c2];
                bl[nj][1] = *(const unsigned*)&Bls[buf][n][kb + c2 + 8];
            }
#pragma unroll
            for (int mi = 0; mi < 2; mi++)
#pragma unroll
                for (int nj = 0; nj < 4; nj++) {
                    mma_bf16(d[mi][nj], ah[mi], bh[nj]);
                    mma_bf16(d[mi][nj], ah[mi], bl[nj]);
                    mma_bf16(d[mi][nj], al[mi], bh[nj]);
                }
        }
        if (c + 1 < nCh) {
            int nbuf = buf ^ 1;
            *(uint4*)&Ahs[nbuf][lrow     ][lcol] = pf[0];
            *(uint4*)&Ahs[nbuf][lrow + 32][lcol] = pf[1];
            *(uint4*)&Als[nbuf][lrow     ][lcol] = pf[2];
            *(uint4*)&Als[nbuf][lrow + 32][lcol] = pf[3];
            *(uint4*)&Bhs[nbuf][lrow     ][lcol] = pf[4];
            *(uint4*)&Bhs[nbuf][lrow + 32][lcol] = pf[5];
            *(uint4*)&Bls[nbuf][lrow     ][lcol] = pf[6];
            *(uint4*)&Bls[nbuf][lrow + 32][lcol] = pf[7];
        }
        __syncthreads();
    }

    // epilogue straight from registers
#pragma unroll
    for (int mi = 0; mi < 2; mi++) {
#pragma unroll
        for (int rr = 0; rr < 2; rr++) {
            int m = bm + wm * 32 + mi * 16 + g + rr * 8;
#pragma unroll
            for (int nj = 0; nj < 4; nj++) {
#pragma unroll
                for (int cc = 0; cc < 2; cc++) {
                    int col = bn + wn * 32 + nj * 8 + c2 + cc;
                    float v = d[mi][nj][rr * 2 + cc];
                    if (MODE == 0) {
                        v += bias[col];
                        int creg = col & 511, region = col >> 9;
                        if (region == 0) {
                            g_q[m * ND + creg] = v;
                        } else if (region == 1) {
                            g_kc[(size_t)l * (NB * NH * NT * NHD) +
                                 (size_t)((m * NH + (creg >> 6)) * NT + t) * NHD + (creg & 63)] = v;
                        } else {
                            g_vc[(size_t)l * (NB * NH * NT * NHD) +
                                 (size_t)((m * NH + (creg >> 6)) * NT + t) * NHD + (creg & 63)] = v;
                        }
                    } else if (MODE == 1) {
                        v = fmaxf(v + bias[col], 0.f);
                        split_store(v, gff_hi, gff_lo, m * NFF + col);
                    } else {
                        g_part[(size_t)z * (NB * ND) + m * ND + col] = v;
                    }
                }
            }
        }
    }
}

// ---------------------------------------------------------------------------
// Fused split-K reduce + bias + residual + LayerNorm (+ bf16 mirror out).
// ---------------------------------------------------------------------------
__global__ void redln_k(const float* __restrict__ bias,
                        const float* __restrict__ gam,
                        const float* __restrict__ bet,
                        int nsplit, int outsel) {
    int b = blockIdx.x, tid = threadIdx.x;   // 256 threads, 2 cols each
    const float* R = outsel ? g_h1 : g_h;
    float v0 = R[b * ND + tid]       + bias[tid];
    float v1 = R[b * ND + tid + 256] + bias[tid + 256];
    for (int z = 0; z < nsplit; z++) {
        v0 += g_part[(size_t)z * (NB * ND) + b * ND + tid];
        v1 += g_part[(size_t)z * (NB * ND) + b * ND + tid + 256];
    }

    __shared__ float sh[8], sh2[8];
    float s = v0 + v1;
#pragma unroll
    for (int o = 16; o; o >>= 1) s += __shfl_xor_sync(0xffffffffu, s, o);
    if ((tid & 31) == 0) sh[tid >> 5] = s;
    __syncthreads();
    float tot = 0.f;
#pragma unroll
    for (int i = 0; i < 8; i++) tot += sh[i];
    float mean = tot * (1.0f / 512.0f);

    float d0 = v0 - mean, d1 = v1 - mean;
    float q = d0 * d0 + d1 * d1;
#pragma unroll
    for (int o = 16; o; o >>= 1) q += __shfl_xor_sync(0xffffffffu, q, o);
    if ((tid & 31) == 0) sh2[tid >> 5] = q;
    __syncthreads();
    float vtot = 0.f;
#pragma unroll
    for (int i = 0; i < 8; i++) vtot += sh2[i];
    float inv = rsqrtf(vtot * (1.0f / 512.0f) + 1e-5f);

    float* out = outsel ? g_h : g_h1;
    bf16* ohi = outsel ? gh_hi : gh1_hi;
    bf16* olo = outsel ? gh_lo : gh1_lo;
    float o0 = d0 * inv * gam[tid]       + bet[tid];
    float o1 = d1 * inv * gam[tid + 256] + bet[tid + 256];
    out[b * ND + tid]       = o0;
    out[b * ND + tid + 256] = o1;
    split_store(o0, ohi, olo, b * ND + tid);
    split_store(o1, ohi, olo, b * ND + tid + 256);
}

// ---------------------------------------------------------------------------
// attention: one warp per (b, h); writes bf16 mirrors of attn output.
// ---------------------------------------------------------------------------
__global__ void attn_k(int t, int l) {
    int wg   = (blockIdx.x << 2) + (threadIdx.x >> 5);
    int lane = threadIdx.x & 31;
    int b = wg >> 3, h = wg & 7;

    const float* qp = g_q + b * ND + h * NHD;
    float q0 = qp[lane], q1 = qp[lane + 32];

    const float* kb = g_kc + (size_t)l * (NB * NH * NT * NHD) + (size_t)(b * NH + h) * NT * NHD;
    const float* vb = g_vc + (size_t)l * (NB * NH * NT * NHD) + (size_t)(b * NH + h) * NT * NHD;

    float sc[NT];
#pragma unroll
    for (int p = 0; p < NT; p++) {
        float s = -1e30f;
        if (p <= t) {
            s = q0 * kb[p * NHD + lane] + q1 * kb[p * NHD + lane + 32];
#pragma unroll
            for (int o = 16; o; o >>= 1) s += __shfl_xor_sync(0xffffffffu, s, o);
            s *= 0.125f;
        }
        sc[p] = s;
    }
    float mx = -1e30f;
#pragma unroll
    for (int p = 0; p < NT; p++) mx = fmaxf(mx, sc[p]);
    float sum = 0.f;
#pragma unroll
    for (int p = 0; p < NT; p++) {
        float e = expf(sc[p] - mx);
        sc[p] = e;
        sum += e;
    }
    float invs = 1.0f / sum;
    float o0 = 0.f, o1 = 0.f;
#pragma unroll
    for (int p = 0; p < NT; p++) {
        if (p <= t) {
            float a = sc[p] * invs;
            o0 = fmaf(a, vb[p * NHD + lane],      o0);
            o1 = fmaf(a, vb[p * NHD + lane + 32], o1);
        }
    }
    split_store(o0, gat_hi, gat_lo, b * ND + h * NHD + lane);
    split_store(o1, gat_hi, gat_lo, b * ND + h * NHD + lane + 32);
}

// ---------------------------------------------------------------------------
// head: y[b,c] = g_h[b,:] @ head_w[:,c] + head_b[c]
// ---------------------------------------------------------------------------
__global__ void head_k(const float* __restrict__ hw,
                       const float* __restrict__ hb,
                       float* __restrict__ out, int t) {
    int b = blockIdx.x;
    int w = threadIdx.x >> 5;        // 0..2 (96 threads)
    int lane = threadIdx.x & 31;
    float acc = 0.f;
#pragma unroll
    for (int i = 0; i < 16; i++) {
        int d = lane + (i << 5);
        acc = fmaf(g_h[b * ND + d], hw[d * 3 + w], acc);
    }
#pragma unroll
    for (int o = 16; o; o >>= 1) acc += __shfl_xor_sync(0xffffffffu, acc, o);
    if (lane == 0) {
        float v = acc + hb[w];
        out[(b * NT + t) * 3 + w] = v;
        g_y[b * 3 + w] = v;
    }
}

// ---------------------------------------------------------------------------
extern "C" void kernel_launch(void* const* d_in, const int* in_sizes, int n_in,
                              void* d_out, int out_size) {
    const float* x    = (const float*)d_in[0];
    const float* ipw  = (const float*)d_in[1];
    const float* ipb  = (const float*)d_in[2];
    const float* qkvw = (const float*)d_in[3];
    const float* qkvb = (const float*)d_in[4];
    const float* outw = (const float*)d_in[5];
    const float* outb = (const float*)d_in[6];
    const float* ln1s = (const float*)d_in[7];
    const float* ln1b = (const float*)d_in[8];
    const float* ffw1 = (const float*)d_in[9];
    const float* ffb1 = (const float*)d_in[10];
    const float* ffw2 = (const float*)d_in[11];
    const float* ffb2 = (const float*)d_in[12];
    const float* ln2s = (const float*)d_in[13];
    const float* ln2b = (const float*)d_in[14];
    const float* hw   = (const float*)d_in[15];
    const float* hb   = (const float*)d_in[16];
    float* out = (float*)d_out;

    (void)in_sizes; (void)n_in; (void)out_size;

    // one-time (per replay) weight transpose + bf16 split: [K,N] -> [N,K]
    bf16 *whi, *wlo;
    for (int l = 0; l < NL; l++) {
        cudaGetSymbolAddress((void**)&whi, wqkv_hi); cudaGetSymbolAddress((void**)&wlo, wqkv_lo);
        wsplit_k<<<dim3(3 * ND / 32, ND / 32), dim3(32, 8)>>>(
            qkvw + (size_t)l * ND * 3 * ND, whi + (size_t)l * 3 * ND * ND,
            wlo + (size_t)l * 3 * ND * ND, ND, 3 * ND);
        cudaGetSymbolAddress((void**)&whi, wout_hi); cudaGetSymbolAddress((void**)&wlo, wout_lo);
        wsplit_k<<<dim3(ND / 32, ND / 32), dim3(32, 8)>>>(
            outw + (size_t)l * ND * ND, whi + (size_t)l * ND * ND,
            wlo + (size_t)l * ND * ND, ND, ND);
        cudaGetSymbolAddress((void**)&whi, wff1_hi); cudaGetSymbolAddress((void**)&wlo, wff1_lo);
        wsplit_k<<<dim3(NFF / 32, ND / 32), dim3(32, 8)>>>(
            ffw1 + (size_t)l * ND * NFF, whi + (size_t)l * NFF * ND,
            wlo + (size_t)l * NFF * ND, ND, NFF);
        cudaGetSymbolAddress((void**)&whi, wff2_hi); cudaGetSymbolAddress((void**)&wlo, wff2_lo);
        wsplit_k<<<dim3(ND / 32, NFF / 32), dim3(32, 8)>>>(
            ffw2 + (size_t)l * NFF * ND, whi + (size_t)l * ND * NFF,
            wlo + (size_t)l * ND * NFF, NFF, ND);
    }

    bf16 *qkvT_hi, *qkvT_lo, *outT_hi, *outT_lo, *ff1T_hi, *ff1T_lo, *ff2T_hi, *ff2T_lo;
    cudaGetSymbolAddress((void**)&qkvT_hi, wqkv_hi); cudaGetSymbolAddress((void**)&qkvT_lo, wqkv_lo);
    cudaGetSymbolAddress((void**)&outT_hi, wout_hi); cudaGetSymbolAddress((void**)&outT_lo, wout_lo);
    cudaGetSymbolAddress((void**)&ff1T_hi, wff1_hi); cudaGetSymbolAddress((void**)&ff1T_lo, wff1_lo);
    cudaGetSymbolAddress((void**)&ff2T_hi, wff2_hi); cudaGetSymbolAddress((void**)&ff2T_lo, wff2_lo);

    for (int t = 0; t < NT; t++) {
        embed_k<<<NB, ND>>>(x, ipw, ipb, t);
        for (int l = 0; l < NL; l++) {
            // QKV: 512x1536, K=512 -> Q / KV cache  (192 CTAs)
            gemmM_k<0><<<dim3(24, 8, 1), 128>>>(
                qkvT_hi + (size_t)l * 3 * ND * ND, qkvT_lo + (size_t)l * 3 * ND * ND,
                qkvb + l * 3 * ND, ND, ND, l, t);
            attn_k<<<NB * NH / 4, 128>>>(t, l);
            // out-proj: 512x512, K=512 split 2 -> partials  (128 CTAs)
            gemmM_k<2><<<dim3(8, 8, 2), 128>>>(
                outT_hi + (size_t)l * ND * ND, outT_lo + (size_t)l * ND * ND,
                outb + l * ND, ND, ND / 2, l, t);
            redln_k<<<NB, 256>>>(outb + l * ND, ln1s + l * ND, ln1b + l * ND, 2, 0);
            // FF1: 512x2048, K=512 -> relu -> gff mirrors  (256 CTAs)
            gemmM_k<1><<<dim3(32, 8, 1), 128>>>(
                ff1T_hi + (size_t)l * NFF * ND, ff1T_lo + (size_t)l * NFF * ND,
                ffb1 + l * NFF, ND, ND, l, t);
            // FF2: 512x512, K=2048 split 4 -> partials  (256 CTAs)
            gemmM_k<3><<<dim3(8, 8, 4), 128>>>(
                ff2T_hi + (size_t)l * ND * NFF, ff2T_lo + (size_t)l * ND * NFF,
                ffb2 + l * ND, NFF, NFF / 4, l, t);
            redln_k<<<NB, 256>>>(ffb2 + l * ND, ln2s + l * ND, ln2b + l * ND, 4, 1);
        }
        head_k<<<NB, 96>>>(hw, hb, out, t);
    }
}